// round 1
// baseline (speedup 1.0000x reference)
#include <cuda_runtime.h>
#include <math.h>

#define BB 32
#define NN 1024

// Per-row scratch (device globals: no runtime allocation allowed)
__device__ float  g_tt[BB];   // tail threshold  (== s[972], replicates quantile mask exactly)
__device__ float  g_t5[BB];   // 5th largest value (top-k mask)
__device__ float  g_lw[BB];   // per-row listwise loss
__device__ double g_pS[BB];   // per-row pairwise weighted sum (upper triangle)
__device__ double g_pC[BB];   // per-row pair count (upper triangle)

__device__ __forceinline__ float ex2a(float x){ float y; asm("ex2.approx.f32 %0, %1;" : "=f"(y) : "f"(x)); return y; }
__device__ __forceinline__ float rcpa(float x){ float y; asm("rcp.approx.f32 %0, %1;" : "=f"(y) : "f"(x)); return y; }

// ---------------------------------------------------------------------------
// Kernel 1: per-row bitonic sort of y_true -> order statistics; zero accums
// ---------------------------------------------------------------------------
__global__ void prep_kernel(const float* __restrict__ yt){
    const int row = blockIdx.x;
    const int tid = threadIdx.x;
    __shared__ float s[NN];
    s[tid] = yt[row * NN + tid];
    __syncthreads();
    for (int k = 2; k <= NN; k <<= 1){
        for (int j = k >> 1; j > 0; j >>= 1){
            int ixj = tid ^ j;
            if (ixj > tid){
                float a = s[tid], b = s[ixj];
                bool up = (tid & k) == 0;
                if ((a > b) == up){ s[tid] = b; s[ixj] = a; }
            }
            __syncthreads();
        }
    }
    if (tid == 0){
        g_tt[row] = s[972];      // tail mask: y >= interpolated-quantile  <=>  y >= s[972]
        g_t5[row] = s[NN - 5];   // top-5 mask: y >= 5th largest
        g_pS[row] = 0.0;
        g_pC[row] = 0.0;
    }
}

// ---------------------------------------------------------------------------
// Kernel 2: per-row listwise weighted cross-entropy
// ---------------------------------------------------------------------------
__global__ void listwise_kernel(const float* __restrict__ yp, const float* __restrict__ yt){
    const int row = blockIdx.x;
    const int tid = threadIdx.x;            // 256 threads
    const float* p = yp + row * NN;
    const float* t = yt + row * NN;
    __shared__ float sh[256];

    // max reductions
    float mp = -3.4e38f, mt = -3.4e38f;
    for (int j = tid; j < NN; j += 256){ mp = fmaxf(mp, p[j]); mt = fmaxf(mt, t[j]); }
    sh[tid] = mp; __syncthreads();
    for (int o = 128; o; o >>= 1){ if (tid < o) sh[tid] = fmaxf(sh[tid], sh[tid + o]); __syncthreads(); }
    mp = sh[0]; __syncthreads();
    sh[tid] = mt; __syncthreads();
    for (int o = 128; o; o >>= 1){ if (tid < o) sh[tid] = fmaxf(sh[tid], sh[tid + o]); __syncthreads(); }
    mt = sh[0]; __syncthreads();

    // exp-sum reductions
    float sp = 0.f, st = 0.f;
    for (int j = tid; j < NN; j += 256){ sp += __expf(p[j] - mp); st += __expf(t[j] - mt); }
    sh[tid] = sp; __syncthreads();
    for (int o = 128; o; o >>= 1){ if (tid < o) sh[tid] += sh[tid + o]; __syncthreads(); }
    sp = sh[0]; __syncthreads();
    sh[tid] = st; __syncthreads();
    for (int o = 128; o; o >>= 1){ if (tid < o) sh[tid] += sh[tid + o]; __syncthreads(); }
    st = sh[0]; __syncthreads();

    const float tt = g_tt[row], t5 = g_t5[row];
    const float rSp = 1.0f / sp, rSt = 1.0f / st;

    float num = 0.f, den = 0.f;
    for (int j = tid; j < NN; j += 256){
        float tv = t[j];
        float w  = ((tv >= tt) ? 10.f : 1.f) * ((tv >= t5) ? 2.f : 1.f);
        float pp = __expf(p[j] - mp) * rSp;
        float tp = __expf(tv   - mt) * rSt;
        num += tp * logf(pp + 1e-12f) * w;
        den += w;
    }
    sh[tid] = num; __syncthreads();
    for (int o = 128; o; o >>= 1){ if (tid < o) sh[tid] += sh[tid + o]; __syncthreads(); }
    num = sh[0]; __syncthreads();
    sh[tid] = den; __syncthreads();
    for (int o = 128; o; o >>= 1){ if (tid < o) sh[tid] += sh[tid + o]; __syncthreads(); }
    den = sh[0];

    if (tid == 0) g_lw[row] = -num / (den + 1e-12f);
}

// ---------------------------------------------------------------------------
// Kernel 3: pairwise loss — upper-triangle 128x128 tiles.
//   sig = 1/(1+exp(-arg)),  arg = -(pi-pj)*sign(ti-tj)
//   exp(-arg) = exp2( (ti>tj ? +1 : -1) * (pi-pj)*log2e )
// ---------------------------------------------------------------------------
__global__ void pairwise_kernel(const float* __restrict__ yp, const float* __restrict__ yt){
    const int row = blockIdx.y;
    // map linear tile id -> (bi, bj) with bi <= bj over 8x8 blocks
    int rem = blockIdx.x, bi = 0;
    while (rem >= 8 - bi){ rem -= 8 - bi; ++bi; }
    const int bj = bi + rem;

    const float* p = yp + row * NN;
    const float* t = yt + row * NN;
    const float tt = g_tt[row], t5 = g_t5[row];
    const int tid = threadIdx.x;            // 128 threads
    const float LOG2E = 1.4426950408889634f;

    __shared__ float4 sj[128];
    {
        int j = bj * 128 + tid;
        float tv = t[j];
        float w  = ((tv >= tt) ? 10.f : 1.f) * ((tv >= t5) ? 2.f : 1.f);
        sj[tid] = make_float4(p[j] * LOG2E, tv, w, 0.f);
    }
    __syncthreads();

    const int   gi  = bi * 128 + tid;
    const float pli = p[gi] * LOG2E;
    const float ti_ = t[gi];
    const float wi  = ((ti_ >= tt) ? 10.f : 1.f) * ((ti_ >= t5) ? 2.f : 1.f);

    float accS = 0.f, accC = 0.f;
    if (bi == bj){
        for (int j = tid + 1; j < 128; ++j){
            float4 c = sj[j];
            float dl = pli - c.x;
            bool  gt = ti_ > c.y;
            float e  = ex2a(gt ? dl : -dl);
            float r  = rcpa(1.0f + e);
            float ne = (ti_ != c.y) ? 1.0f : 0.0f;
            accS += (wi + c.z) * ne * r;
            accC += ne;
        }
    } else {
        #pragma unroll 8
        for (int j = 0; j < 128; ++j){
            float4 c = sj[j];
            float dl = pli - c.x;
            bool  gt = ti_ > c.y;
            float e  = ex2a(gt ? dl : -dl);
            float r  = rcpa(1.0f + e);
            float ne = (ti_ != c.y) ? 1.0f : 0.0f;
            accS += (wi + c.z) * ne * r;
            accC += ne;
        }
    }

    // block reduce (4 warps)
    const unsigned fm = 0xffffffffu;
    for (int o = 16; o; o >>= 1){
        accS += __shfl_down_sync(fm, accS, o);
        accC += __shfl_down_sync(fm, accC, o);
    }
    __shared__ float rs[4], rc[4];
    const int wq = tid >> 5, ln = tid & 31;
    if (ln == 0){ rs[wq] = accS; rc[wq] = accC; }
    __syncthreads();
    if (tid == 0){
        float S = rs[0] + rs[1] + rs[2] + rs[3];
        float C = rc[0] + rc[1] + rc[2] + rc[3];
        atomicAdd(&g_pS[row], (double)S);
        atomicAdd(&g_pC[row], (double)C);
    }
}

// ---------------------------------------------------------------------------
// Kernel 4: combine per-row results -> scalar
// ---------------------------------------------------------------------------
__global__ void final_kernel(float* __restrict__ out){
    const int r = threadIdx.x;              // 32 threads = 1 warp
    double S = g_pS[r] * 2.0;               // ordered pairs = 2 * upper triangle
    double C = g_pC[r] * 2.0;
    if (C < 1.0) C = 1.0;
    float v = g_lw[r] + (float)(S / C);
    for (int o = 16; o; o >>= 1) v += __shfl_down_sync(0xffffffffu, v, o);
    if (r == 0) out[0] = v * (1.0f / 32.0f);
}

// ---------------------------------------------------------------------------
extern "C" void kernel_launch(void* const* d_in, const int* in_sizes, int n_in,
                              void* d_out, int out_size){
    const float* yp = (const float*)d_in[0];   // y_pred [32,1024]
    const float* yt = (const float*)d_in[1];   // y_true [32,1024]
    float* out = (float*)d_out;

    prep_kernel<<<BB, NN>>>(yt);
    listwise_kernel<<<BB, 256>>>(yp, yt);
    pairwise_kernel<<<dim3(36, BB), 128>>>(yp, yt);
    final_kernel<<<1, 32>>>(out);
}